// round 8
// baseline (speedup 1.0000x reference)
#include <cuda_runtime.h>
#include <cuda_bf16.h>
#include <math.h>

#define BSZ   4096
#define TSZ   1024
#define DIN   2
#define EMD   128
#define CELL  128
#define DOUT  5
#define GATES 512
#define NCTA  128
#define ROWS  32
#define NTHR  512
#define STR   136            /* A-plane row stride (bf16): bank offset 4/row -> conflict-free */
#define HSST  132
#define WOST  132
#define NBF   (16*16*4*32*8) /* 262144 bf16 = 512KB: [kt][w][nt][lane][hi x4 | lo x4] */

typedef unsigned int u32;

/* ---------------- persistent device scratch ---------------- */
__device__ __nv_bfloat16 g_B[NBF];
__device__ float g_bias[GATES];

/* ---------------- helpers ---------------- */
__device__ __forceinline__ float sigm(float x) {
    return __fdividef(1.0f, 1.0f + __expf(-x));
}
__device__ __forceinline__ float tanh_f(float x) {
    float e = __expf(-2.0f * fabsf(x));
    float r = __fdividef(1.0f - e, 1.0f + e);
    return copysignf(r, x);
}
__device__ __forceinline__ void mma16816(float* d, const u32* a, u32 b0, u32 b1) {
    asm("mma.sync.aligned.m16n8k16.row.col.f32.bf16.bf16.f32 "
        "{%0,%1,%2,%3}, {%4,%5,%6,%7}, {%8,%9}, {%0,%1,%2,%3};"
        : "+f"(d[0]), "+f"(d[1]), "+f"(d[2]), "+f"(d[3])
        : "r"(a[0]), "r"(a[1]), "r"(a[2]), "r"(a[3]), "r"(b0), "r"(b1));
}
__device__ __forceinline__ void ldmat4(u32* r, u32 addr) {
    asm volatile("ldmatrix.sync.aligned.m8n8.x4.shared.b16 {%0,%1,%2,%3}, [%4];"
        : "=r"(r[0]), "=r"(r[1]), "=r"(r[2]), "=r"(r[3]) : "r"(addr));
}

/* ---------------- setup: bf16 hi/lo split weights into mma B fragments ----------------
 * idx = ((((kt*16 + w)*4 + nt)*32 + l)*2 + p)*4 + j  (p: 0=hi, 1=lo)
 * k = kt*16 + 2*(l&3) + (j&1) + 8*(j>>1);  n = nt*128 + 8*w + (l>>2). */
__global__ void setup_kernel(const float* __restrict__ W_ih, const float* __restrict__ W_hh,
                             const float* __restrict__ b_ih, const float* __restrict__ b_hh) {
    int idx = blockIdx.x * blockDim.x + threadIdx.x;
    if (idx < NBF) {
        int j  = idx & 3;
        int p  = (idx >> 2) & 1;
        int l  = (idx >> 3) & 31;
        int nt = (idx >> 8) & 3;
        int w  = (idx >> 10) & 15;
        int kt = idx >> 14;
        int k  = kt * 16 + 2 * (l & 3) + (j & 1) + 8 * (j >> 1);
        int n  = nt * 128 + 8 * w + (l >> 2);
        float v = (k < EMD) ? W_ih[n * EMD + k] : W_hh[n * CELL + (k - EMD)];
        __nv_bfloat16 hi = __float2bfloat16_rn(v);
        g_B[idx] = p ? __float2bfloat16_rn(v - __bfloat162float(hi)) : hi;
    }
    if (idx < GATES) g_bias[idx] = b_ih[idx] + b_hh[idx];
}

/* ---------------- smem layout (bytes) ----------------
 * plane = 32*STR*2 = 8704 B
 * AeHi0 0      AeHi1 8704   AeLo0 17408  AeLo1 26112
 * AhHi  34816  AhLo  43520
 * Hs    52224 (16896)  WoS 69120 (2640)  WeS 71760 (1024)
 * beS   72784 (512)    xsb 73296 (2*32*8 = 512)  -> total 73808 */
#define OFF_AEHI0 0
#define OFF_AEHI1 8704
#define OFF_AELO0 17408
#define OFF_AELO1 26112
#define OFF_AHHI  34816
#define OFF_AHLO  43520
#define OFF_HS    52224
#define OFF_WOS   69120
#define OFF_WES   71760
#define OFF_BES   72784
#define OFF_XSB   73296
#define SMEM_BYTES 73808

__global__ void __launch_bounds__(NTHR, 1)
lstm_persist(const float* __restrict__ inputs,
             const float* __restrict__ We,  const float* __restrict__ be,
             const float* __restrict__ Wo,  const float* __restrict__ bov,
             float* __restrict__ out) {
    extern __shared__ char smc[];
    __nv_bfloat16* AeHi[2] = { (__nv_bfloat16*)(smc + OFF_AEHI0), (__nv_bfloat16*)(smc + OFF_AEHI1) };
    __nv_bfloat16* AeLo[2] = { (__nv_bfloat16*)(smc + OFF_AELO0), (__nv_bfloat16*)(smc + OFF_AELO1) };
    __nv_bfloat16* AhHi = (__nv_bfloat16*)(smc + OFF_AHHI);
    __nv_bfloat16* AhLo = (__nv_bfloat16*)(smc + OFF_AHLO);
    float*  Hs  = (float*)(smc + OFF_HS);
    float*  WoS = (float*)(smc + OFF_WOS);
    float*  WeS = (float*)(smc + OFF_WES);
    float*  beS = (float*)(smc + OFF_BES);
    float2* xsb = (float2*)(smc + OFF_XSB);   /* [2][32] */

    const int tid  = threadIdx.x;
    const int row0 = blockIdx.x * ROWS;
    const int w    = tid >> 5;
    const int l    = tid & 31;
    const int r0   = l >> 2;
    const int cp   = l & 3;
    const int cell0 = 8 * w + 2 * cp;

    /* per-lane ldmatrix address offset (bytes within a plane) */
    const int rl = (l & 7) + ((l >> 3) & 1) * 8;
    const int kl = (l >> 4) * 8;
    const u32 sb = (u32)__cvta_generic_to_shared(smc);
    const u32 aoff = (u32)((rl * STR + kl) * 2);

    /* preload small weights */
    for (int i = tid; i < DOUT * CELL; i += NTHR) WoS[(i / CELL) * WOST + (i % CELL)] = Wo[i];
    for (int i = tid; i < EMD; i += NTHR) {
        WeS[2 * i] = We[2 * i]; WeS[2 * i + 1] = We[2 * i + 1]; beS[i] = be[i];
    }
    /* zero h planes (h0 = 0) */
    for (int i = tid; i < ROWS * STR; i += NTHR) {
        AhHi[i] = __float2bfloat16_rn(0.0f);
        AhLo[i] = __float2bfloat16_rn(0.0f);
    }
    /* stage xs(0) */
    if (tid < ROWS)
        xsb[tid] = ((const float2*)inputs)[(size_t)(row0 + tid) * TSZ];

    /* per-thread gate biases */
    float bia[4][2];
#pragma unroll
    for (int nt = 0; nt < 4; nt++) {
        bia[nt][0] = g_bias[nt * 128 + cell0];
        bia[nt][1] = g_bias[nt * 128 + cell0 + 1];
    }
    float D[2][4][4];
#pragma unroll
    for (int mt = 0; mt < 2; mt++)
#pragma unroll
        for (int nt = 0; nt < 4; nt++) {
            D[mt][nt][0] = bia[nt][0]; D[mt][nt][1] = bia[nt][1];
            D[mt][nt][2] = bia[nt][0]; D[mt][nt][3] = bia[nt][1];
        }
    float cst[8];
#pragma unroll
    for (int i = 0; i < 8; i++) cst[i] = 0.0f;

    const float bo_r = (tid < ROWS * DOUT * 2) ? bov[(tid % 10) >> 1] : 0.0f;
    const int ej  = tid >> 2;
    const int er0 = (tid & 3) * 8;

    __syncthreads();
    /* e(0) into buffer 0 */
    {
        float w0 = WeS[2 * ej], w1 = WeS[2 * ej + 1], bj = beS[ej];
#pragma unroll
        for (int i = 0; i < 8; i++) {
            int r = er0 + i;
            float2 x = xsb[r];
            float e = fmaxf(fmaf(w0, x.x, fmaf(w1, x.y, bj)), 0.0f);
            __nv_bfloat16 hi = __float2bfloat16_rn(e);
            AeHi[0][r * STR + ej] = hi;
            AeLo[0][r * STR + ej] = __float2bfloat16_rn(e - __bfloat162float(hi));
        }
    }
    __syncthreads();

    const uint4* Bp = (const uint4*)g_B;   /* idx: kt*2048 + w*128 + nt*32 + l */
    const u32 bbase = w * 128 + l;

    for (int t = 0; t < TSZ; t++) {
        /* stage x(t+1) into the alternate xs buffer (consumed after S_a) */
        if (t < TSZ - 1 && tid < ROWS)
            xsb[((t + 1) & 1) * ROWS + tid] =
                ((const float2*)inputs)[(size_t)(row0 + tid) * TSZ + t + 1];

        /* ---- GEMM: 16 kt; kt<8 from e-planes (buf t&1), kt>=8 from h-planes ---- */
        const u32 eHiB = sb + (((t & 1) ? OFF_AEHI1 : OFF_AEHI0)) + aoff;
        const u32 eLoB = sb + (((t & 1) ? OFF_AELO1 : OFF_AELO0)) + aoff;
        const u32 hHiB = sb + OFF_AHHI + aoff;
        const u32 hLoB = sb + OFF_AHLO + aoff;

        uint4 Bv[2][4];
#pragma unroll
        for (int nt = 0; nt < 4; nt++) Bv[0][nt] = __ldg(Bp + bbase + nt * 32);

#pragma unroll
        for (int kt = 0; kt < 16; kt++) {
            const int cur = kt & 1;
            if (kt < 15) {
#pragma unroll
                for (int nt = 0; nt < 4; nt++)
                    Bv[cur ^ 1][nt] = __ldg(Bp + (kt + 1) * 2048 + bbase + nt * 32);
            }
            const u32 hiB = (kt < 8) ? (eHiB + kt * 32) : (hHiB + (kt - 8) * 32);
            const u32 loB = (kt < 8) ? (eLoB + kt * 32) : (hLoB + (kt - 8) * 32);
#pragma unroll
            for (int mt = 0; mt < 2; mt++) {
                u32 Ah[4], Al[4];
                ldmat4(Ah, hiB + mt * (16 * STR * 2));
                ldmat4(Al, loB + mt * (16 * STR * 2));
#pragma unroll
                for (int nt = 0; nt < 4; nt++)   /* hi * Bhi */
                    mma16816(D[mt][nt], Ah, Bv[cur][nt].x, Bv[cur][nt].y);
#pragma unroll
                for (int nt = 0; nt < 4; nt++)   /* hi * Blo */
                    mma16816(D[mt][nt], Ah, Bv[cur][nt].z, Bv[cur][nt].w);
#pragma unroll
                for (int nt = 0; nt < 4; nt++)   /* lo * Bhi */
                    mma16816(D[mt][nt], Al, Bv[cur][nt].x, Bv[cur][nt].y);
            }
        }

        /* ---- pointwise in registers ---- */
        float hv[8];
#pragma unroll
        for (int mt = 0; mt < 2; mt++)
#pragma unroll
            for (int half = 0; half < 2; half++)
#pragma unroll
                for (int cc = 0; cc < 2; cc++) {
                    const int e = 2 * half + cc;
                    float iv = sigm(D[mt][0][e]);
                    float fv = sigm(D[mt][1][e]);
                    float gv = tanh_f(D[mt][2][e]);
                    float ov = sigm(D[mt][3][e]);
                    const int ci = mt * 4 + half * 2 + cc;
                    cst[ci] = fmaf(fv, cst[ci], iv * gv);
                    hv[ci] = ov * tanh_f(cst[ci]);
                    D[mt][0][e] = bia[0][cc]; D[mt][1][e] = bia[1][cc];
                    D[mt][2][e] = bia[2][cc]; D[mt][3][e] = bia[3][cc];
                }

        __syncthreads();   /* S_a: all GEMM reads of A planes complete */

        /* write h (hi/lo planes + fp32 Hs) */
#pragma unroll
        for (int mt = 0; mt < 2; mt++)
#pragma unroll
            for (int half = 0; half < 2; half++) {
                const int r = mt * 16 + r0 + 8 * half;
                const int ci = mt * 4 + half * 2;
                float h0 = hv[ci], h1 = hv[ci + 1];
                *(float2*)&Hs[r * HSST + cell0] = make_float2(h0, h1);
                __nv_bfloat16 b0 = __float2bfloat16_rn(h0);
                __nv_bfloat16 b1 = __float2bfloat16_rn(h1);
                *(__nv_bfloat162*)&AhHi[r * STR + cell0] = __nv_bfloat162(b0, b1);
                *(__nv_bfloat162*)&AhLo[r * STR + cell0] = __nv_bfloat162(
                    __float2bfloat16_rn(h0 - __bfloat162float(b0)),
                    __float2bfloat16_rn(h1 - __bfloat162float(b1)));
            }

        /* e(t+1) into alternate e-buffer (depends only on x) */
        if (t < TSZ - 1) {
            const int nb = (t + 1) & 1;
            float w0 = WeS[2 * ej], w1 = WeS[2 * ej + 1], bj = beS[ej];
            const float2* xp = xsb + nb * ROWS;
#pragma unroll
            for (int i = 0; i < 8; i++) {
                int r = er0 + i;
                float2 x = xp[r];
                float e = fmaxf(fmaf(w0, x.x, fmaf(w1, x.y, bj)), 0.0f);
                __nv_bfloat16 hi = __float2bfloat16_rn(e);
                AeHi[nb][r * STR + ej] = hi;
                AeLo[nb][r * STR + ej] = __float2bfloat16_rn(e - __bfloat162float(hi));
            }
        }

        __syncthreads();   /* S_b: h planes + Hs visible */

        /* ---- y-phase: 2 threads per output, overlaps with next GEMM ---- */
        if (tid < ROWS * DOUT * 2) {
            int r = tid / 10, q = tid % 10;
            int d = q >> 1, half = q & 1;
            const float* hrow = Hs + r * HSST + 64 * half;
            const float* wrow = WoS + d * WOST + 64 * half;
            float s = 0.0f;
#pragma unroll 16
            for (int j = 0; j < 64; j++) s = fmaf(hrow[j], wrow[j], s);
            s += __shfl_xor_sync(0xffffffffu, s, 1);
            if (!half)
                out[((size_t)(row0 + r) * TSZ + t) * DOUT + d] = s + bo_r;
        }
    }

    /* ---- tail: final h (Hs, coalesced) and c (registers) ---- */
    size_t baseH = (size_t)BSZ * TSZ * DOUT;
    size_t baseC = baseH + (size_t)BSZ * CELL;
#pragma unroll
    for (int i = 0; i < 8; i++) {
        int idx = tid + i * NTHR;
        int r = idx >> 7, c = idx & 127;
        out[baseH + (size_t)(row0 + r) * CELL + c] = Hs[r * HSST + c];
    }
#pragma unroll
    for (int mt = 0; mt < 2; mt++)
#pragma unroll
        for (int half = 0; half < 2; half++) {
            int r = mt * 16 + r0 + 8 * half;
            *(float2*)&out[baseC + (size_t)(row0 + r) * CELL + cell0] =
                make_float2(cst[mt * 4 + half * 2], cst[mt * 4 + half * 2 + 1]);
        }
}

/* ---------------- launch: 2 graph nodes ---------------- */
extern "C" void kernel_launch(void* const* d_in, const int* in_sizes, int n_in,
                              void* d_out, int out_size) {
    const float* inputs = (const float*)d_in[0];
    const float* We     = (const float*)d_in[1];
    const float* be     = (const float*)d_in[2];
    const float* W_ih   = (const float*)d_in[3];
    const float* W_hh   = (const float*)d_in[4];
    const float* b_ih   = (const float*)d_in[5];
    const float* b_hh   = (const float*)d_in[6];
    const float* Wo     = (const float*)d_in[7];
    const float* bo     = (const float*)d_in[8];
    float* out = (float*)d_out;

    static int smem_set = 0;
    if (!smem_set) {
        cudaFuncSetAttribute(lstm_persist, cudaFuncAttributeMaxDynamicSharedMemorySize,
                             SMEM_BYTES);
        smem_set = 1;
    }

    setup_kernel<<<(NBF + 255) / 256, 256>>>(W_ih, W_hh, b_ih, b_hh);
    lstm_persist<<<NCTA, NTHR, SMEM_BYTES>>>(inputs, We, be, Wo, bo, out);
}